// round 9
// baseline (speedup 1.0000x reference)
#include <cuda_runtime.h>
#include <cuda_bf16.h>

#define FFT_N 4096
#define TPB   256   // = FFT_N / 16, radix-16, 3 stages
#define NCTA  592   // 4 CTAs/SM * 148 SMs, persistent grid-stride

// XOR swizzle: conflict-free for every access pattern in this kernel
__device__ __forceinline__ int sw(int i) { return i ^ ((i >> 4) & 15); }

// ---------------- packed complex: (re, im) in one 64-bit reg pair ----------
typedef unsigned long long c64;

__device__ __forceinline__ c64 mkc(float x, float y) {
    c64 r; asm("mov.b64 %0, {%1, %2};" : "=l"(r) : "f"(x), "f"(y)); return r;
}
__device__ __forceinline__ void unc(c64 a, float& x, float& y) {
    asm("mov.b64 {%0, %1}, %2;" : "=f"(x), "=f"(y) : "l"(a));
}
__device__ __forceinline__ c64 cadd(c64 a, c64 b) {
    c64 r; asm("add.rn.f32x2 %0, %1, %2;" : "=l"(r) : "l"(a), "l"(b)); return r;
}
__device__ __forceinline__ c64 csub(c64 a, c64 b) {
    c64 r; asm("sub.rn.f32x2 %0, %1, %2;" : "=l"(r) : "l"(a), "l"(b)); return r;
}
// (x,y) -> (y,x): register-pair movs only (usually free after allocation)
__device__ __forceinline__ c64 cswap(c64 a) {
    float x, y; unc(a, x, y); return mkc(y, x);
}
// multiply by -i : (x,y) -> (y,-x)  (one sign-bit xor on the ALU pipe)
__device__ __forceinline__ c64 cmul_mi(c64 a) {
    float x, y; unc(a, x, y);
    return mkc(y, __uint_as_float(__float_as_uint(x) ^ 0x80000000u));
}
// a * w where wrr=(wr,wr), wni=(-wi,wi): res = a*wrr + swap(a)*wni
__device__ __forceinline__ c64 cmul_p(c64 a, c64 wrr, c64 wni) {
    c64 t, r;
    asm("mul.rn.f32x2 %0, %1, %2;" : "=l"(t) : "l"(a), "l"(wrr));
    asm("fma.rn.f32x2 %0, %1, %2, %3;" : "=l"(r) : "l"(cswap(a)), "l"(wni), "l"(t));
    return r;
}

// In-place natural-order DFT4 (packed): x[k] <- sum_n x[n] W4^{nk}, W4 = -i
__device__ __forceinline__ void dft4(c64& x0, c64& x1, c64& x2, c64& x3)
{
    c64 t0 = cadd(x0, x2);
    c64 t1 = csub(x0, x2);
    c64 t2 = cadd(x1, x3);
    c64 t3 = cmul_mi(csub(x1, x3));
    x0 = cadd(t0, t2);
    x1 = cadd(t1, t3);
    x2 = csub(t0, t2);
    x3 = csub(t1, t3);
}

#define C8f 0.92387953251128675613f
#define S8f 0.38268343236508977173f
#define R2f 0.70710678118654752440f

// DFT16 on natural-order input a[0..15]. On exit, slot a[k1 + 4*k2] holds
// output bin X[k2 + 4*k1]; callers apply perm16(i) at the store.
__device__ __forceinline__ void dft16(c64* a)
{
    dft4(a[0], a[4], a[8],  a[12]);
    dft4(a[1], a[5], a[9],  a[13]);
    dft4(a[2], a[6], a[10], a[14]);
    dft4(a[3], a[7], a[11], a[15]);

    a[5]  = cmul_p(a[5],  mkc( C8f,  C8f), mkc( S8f, -S8f));  // W^1 = ( c8,-s8)
    a[6]  = cmul_p(a[6],  mkc( R2f,  R2f), mkc( R2f, -R2f));  // W^2 = ( r2,-r2)
    a[7]  = cmul_p(a[7],  mkc( S8f,  S8f), mkc( C8f, -C8f));  // W^3 = ( s8,-c8)
    a[9]  = cmul_p(a[9],  mkc( R2f,  R2f), mkc( R2f, -R2f));  // W^2
    a[10] = cmul_mi(a[10]);                                   // W^4 = -i
    a[11] = cmul_p(a[11], mkc(-R2f, -R2f), mkc( R2f, -R2f));  // W^6 = (-r2,-r2)
    a[13] = cmul_p(a[13], mkc( S8f,  S8f), mkc( C8f, -C8f));  // W^3
    a[14] = cmul_p(a[14], mkc(-R2f, -R2f), mkc( R2f, -R2f));  // W^6
    a[15] = cmul_p(a[15], mkc(-C8f, -C8f), mkc(-S8f,  S8f));  // W^9 = (-c8, s8)

    dft4(a[0],  a[1],  a[2],  a[3]);
    dft4(a[4],  a[5],  a[6],  a[7]);
    dft4(a[8],  a[9],  a[10], a[11]);
    dft4(a[12], a[13], a[14], a[15]);
}

// output-bin index held in slot i after dft16
__device__ __forceinline__ int perm16(int i) { return (i >> 2) | ((i & 3) << 2); }

// Stockham inter-stage twiddle: a[r] *= exp(-2*pi*i * r * (j mod Ns) / (16*Ns)).
// Binary powers w, w^2, w^4, w^8 (depth 3), applied per set bit of r.
template <int Ns>
__device__ __forceinline__ void twiddle16(c64* a, int j)
{
    const int   p = j & (Ns - 1);
    const float k = -6.2831853071795864769f / (16.0f * (float)Ns);
    float s, c;
    __sincosf(k * (float)p, &s, &c);            // |angle| < 2*pi/16 -> accurate
    const float c2 = c  * c  - s  * s,  s2 = 2.0f * c  * s;
    const float c4 = c2 * c2 - s2 * s2, s4 = 2.0f * c2 * s2;
    const float c8 = c4 * c4 - s4 * s4, s8 = 2.0f * c4 * s4;

    const c64 w1r = mkc(c,  c),  w1n = mkc(-s,  s);
    const c64 w2r = mkc(c2, c2), w2n = mkc(-s2, s2);
    const c64 w4r = mkc(c4, c4), w4n = mkc(-s4, s4);
    const c64 w8r = mkc(c8, c8), w8n = mkc(-s8, s8);
#pragma unroll
    for (int r = 1; r < 16; ++r) {
        if (r & 1) a[r] = cmul_p(a[r], w1r, w1n);
        if (r & 2) a[r] = cmul_p(a[r], w2r, w2n);
        if (r & 4) a[r] = cmul_p(a[r], w4r, w4n);
        if (r & 8) a[r] = cmul_p(a[r], w8r, w8n);
    }
}

__global__ void __launch_bounds__(TPB, 4)
fft4096_r16(const float* __restrict__ xre, const float* __restrict__ xim,
            float* __restrict__ yre, float* __restrict__ yim, int rows)
{
    __shared__ c64 buf[FFT_N];                 // 32 KB, XOR-swizzled

    const int j  = threadIdx.x;                // 0..255
    const int jx = j ^ (j >> 4);               // pre-swizzled read index:
                                               // sw(j + 256r) == jx + 256r

    for (int row = blockIdx.x; row < rows; row += NCTA) {
        const size_t base = (size_t)row * FFT_N;
        c64 a[16];

        // ---- stage 0 (Ns=1): coalesced front-batched global load ----
#pragma unroll
        for (int r = 0; r < 16; ++r) {
            const int idx = j + (r << 8);
            a[r] = mkc(xre[base + idx], xim[base + idx]);
        }
        dft16(a);
#pragma unroll
        for (int i = 0; i < 16; ++i)
            buf[sw((j << 4) + perm16(i))] = a[i];  // idxD = 16j, +m
        __syncthreads();

        // ---- stage 1 (Ns=16) ----
#pragma unroll
        for (int r = 0; r < 16; ++r)
            a[r] = buf[jx + (r << 8)];
        __syncthreads();                       // in-place: reads before writes
        twiddle16<16>(a, j);
        dft16(a);
        {
            const int idxD = ((j >> 4) << 8) | (j & 15);
#pragma unroll
            for (int i = 0; i < 16; ++i)
                buf[sw(idxD + (perm16(i) << 4))] = a[i];
        }
        __syncthreads();

        // ---- stage 2 (Ns=256): idxD = j, coalesced global store ----
#pragma unroll
        for (int r = 0; r < 16; ++r)
            a[r] = buf[jx + (r << 8)];
        __syncthreads();   // fence: next iteration's buf writes vs these reads
        twiddle16<256>(a, j);
        dft16(a);
#pragma unroll
        for (int i = 0; i < 16; ++i) {
            const int idx = j + (perm16(i) << 8);
            float re, im; unc(a[i], re, im);
            yre[base + idx] = re;
            yim[base + idx] = im;
        }
    }
}

extern "C" void kernel_launch(void* const* d_in, const int* in_sizes, int n_in,
                              void* d_out, int out_size)
{
    const float* xre = (const float*)d_in[0];
    const float* xim = (const float*)d_in[1];
    float*       out = (float*)d_out;

    const int rows = in_sizes[0] / FFT_N;      // 4096
    float* yre = out;
    float* yim = out + (size_t)rows * FFT_N;   // output tuple: [y_re | y_im]

    const int grid = rows < NCTA ? rows : NCTA;
    fft4096_r16<<<grid, TPB>>>(xre, xim, yre, yim, rows);
}

// round 10
// speedup vs baseline: 1.1454x; 1.1454x over previous
#include <cuda_runtime.h>
#include <cuda_bf16.h>

#define FFT_N 4096
#define TPB   256   // = FFT_N / 16, radix-16, 3 stages

// XOR swizzle: conflict-free for every access pattern in this kernel
__device__ __forceinline__ int sw(int i) { return i ^ ((i >> 4) & 15); }

// ---------------- packed complex: (re, im) in one 64-bit reg pair ----------
typedef unsigned long long c64;

__device__ __forceinline__ c64 mkc(float x, float y) {
    c64 r; asm("mov.b64 %0, {%1, %2};" : "=l"(r) : "f"(x), "f"(y)); return r;
}
__device__ __forceinline__ void unc(c64 a, float& x, float& y) {
    asm("mov.b64 {%0, %1}, %2;" : "=f"(x), "=f"(y) : "l"(a));
}
__device__ __forceinline__ c64 cadd(c64 a, c64 b) {
    c64 r; asm("add.rn.f32x2 %0, %1, %2;" : "=l"(r) : "l"(a), "l"(b)); return r;
}
__device__ __forceinline__ c64 csub(c64 a, c64 b) {
    c64 r; asm("sub.rn.f32x2 %0, %1, %2;" : "=l"(r) : "l"(a), "l"(b)); return r;
}
// (x,y) -> (y,x): register-pair movs only (usually free after allocation)
__device__ __forceinline__ c64 cswap(c64 a) {
    float x, y; unc(a, x, y); return mkc(y, x);
}
// multiply by -i : (x,y) -> (y,-x)  (one sign-bit xor on the ALU pipe)
__device__ __forceinline__ c64 cmul_mi(c64 a) {
    float x, y; unc(a, x, y);
    return mkc(y, __uint_as_float(__float_as_uint(x) ^ 0x80000000u));
}
// a * w where wrr=(wr,wr), wni=(-wi,wi): res = a*wrr + swap(a)*wni
__device__ __forceinline__ c64 cmul_p(c64 a, c64 wrr, c64 wni) {
    c64 t, r;
    asm("mul.rn.f32x2 %0, %1, %2;" : "=l"(t) : "l"(a), "l"(wrr));
    asm("fma.rn.f32x2 %0, %1, %2, %3;" : "=l"(r) : "l"(cswap(a)), "l"(wni), "l"(t));
    return r;
}

// In-place natural-order DFT4 (packed): x[k] <- sum_n x[n] W4^{nk}, W4 = -i
__device__ __forceinline__ void dft4(c64& x0, c64& x1, c64& x2, c64& x3)
{
    c64 t0 = cadd(x0, x2);
    c64 t1 = csub(x0, x2);
    c64 t2 = cadd(x1, x3);
    c64 t3 = cmul_mi(csub(x1, x3));
    x0 = cadd(t0, t2);
    x1 = cadd(t1, t3);
    x2 = csub(t0, t2);
    x3 = csub(t1, t3);
}

#define C8f 0.92387953251128675613f
#define S8f 0.38268343236508977173f
#define R2f 0.70710678118654752440f

// DFT16 on natural-order input a[0..15]. On exit, slot a[k1 + 4*k2] holds
// output bin X[k2 + 4*k1]; callers apply perm16(i) at the store.
__device__ __forceinline__ void dft16(c64* a)
{
    dft4(a[0], a[4], a[8],  a[12]);
    dft4(a[1], a[5], a[9],  a[13]);
    dft4(a[2], a[6], a[10], a[14]);
    dft4(a[3], a[7], a[11], a[15]);

    a[5]  = cmul_p(a[5],  mkc( C8f,  C8f), mkc( S8f, -S8f));  // W^1 = ( c8,-s8)
    a[6]  = cmul_p(a[6],  mkc( R2f,  R2f), mkc( R2f, -R2f));  // W^2 = ( r2,-r2)
    a[7]  = cmul_p(a[7],  mkc( S8f,  S8f), mkc( C8f, -C8f));  // W^3 = ( s8,-c8)
    a[9]  = cmul_p(a[9],  mkc( R2f,  R2f), mkc( R2f, -R2f));  // W^2
    a[10] = cmul_mi(a[10]);                                   // W^4 = -i
    a[11] = cmul_p(a[11], mkc(-R2f, -R2f), mkc( R2f, -R2f));  // W^6 = (-r2,-r2)
    a[13] = cmul_p(a[13], mkc( S8f,  S8f), mkc( C8f, -C8f));  // W^3
    a[14] = cmul_p(a[14], mkc(-R2f, -R2f), mkc( R2f, -R2f));  // W^6
    a[15] = cmul_p(a[15], mkc(-C8f, -C8f), mkc(-S8f,  S8f));  // W^9 = (-c8, s8)

    dft4(a[0],  a[1],  a[2],  a[3]);
    dft4(a[4],  a[5],  a[6],  a[7]);
    dft4(a[8],  a[9],  a[10], a[11]);
    dft4(a[12], a[13], a[14], a[15]);
}

// output-bin index held in slot i after dft16
__device__ __forceinline__ int perm16(int i) { return (i >> 2) | ((i & 3) << 2); }

// Stockham inter-stage twiddle: a[r] *= exp(-2*pi*i * r * (j mod Ns) / (16*Ns)).
// Binary powers w, w^2, w^4, w^8 (depth 3), applied per set bit of r.
template <int Ns>
__device__ __forceinline__ void twiddle16(c64* a, int j)
{
    const int   p = j & (Ns - 1);
    const float k = -6.2831853071795864769f / (16.0f * (float)Ns);
    float s, c;
    __sincosf(k * (float)p, &s, &c);            // |angle| < 2*pi/16 -> accurate
    const float c2 = c  * c  - s  * s,  s2 = 2.0f * c  * s;
    const float c4 = c2 * c2 - s2 * s2, s4 = 2.0f * c2 * s2;
    const float c8 = c4 * c4 - s4 * s4, s8 = 2.0f * c4 * s4;

    const c64 w1r = mkc(c,  c),  w1n = mkc(-s,  s);
    const c64 w2r = mkc(c2, c2), w2n = mkc(-s2, s2);
    const c64 w4r = mkc(c4, c4), w4n = mkc(-s4, s4);
    const c64 w8r = mkc(c8, c8), w8n = mkc(-s8, s8);
#pragma unroll
    for (int r = 1; r < 16; ++r) {
        if (r & 1) a[r] = cmul_p(a[r], w1r, w1n);
        if (r & 2) a[r] = cmul_p(a[r], w2r, w2n);
        if (r & 4) a[r] = cmul_p(a[r], w4r, w4n);
        if (r & 8) a[r] = cmul_p(a[r], w8r, w8n);
    }
}

__global__ void __launch_bounds__(TPB, 4)
fft4096_r16(const float* __restrict__ xre, const float* __restrict__ xim,
            float* __restrict__ yre, float* __restrict__ yim)
{
    __shared__ c64 buf[FFT_N];                 // 32 KB, XOR-swizzled

    const int    j    = threadIdx.x;           // 0..255
    const size_t base = (size_t)blockIdx.x * FFT_N;

    c64 a[16];

    // ---- stage 0 (Ns = 1): coalesced global load, no inter-stage twiddle ----
#pragma unroll
    for (int r = 0; r < 16; ++r) {
        const int idx = j + (r << 8);
        a[r] = mkc(xre[base + idx], xim[base + idx]);
    }
    dft16(a);
#pragma unroll
    for (int i = 0; i < 16; ++i)
        buf[sw((j << 4) + perm16(i))] = a[i];  // idxD = 16j, +m
    __syncthreads();

    // ---- stage 1 (Ns = 16) ----
#pragma unroll
    for (int r = 0; r < 16; ++r)
        a[r] = buf[sw(j + (r << 8))];
    // compute BEFORE the hazard barrier: reads are done, writes come after.
    // Keeps the post-barrier critical section down to the 16 STS.
    twiddle16<16>(a, j);
    dft16(a);
    __syncthreads();                           // in-place: reads before writes
    {
        const int idxD = ((j >> 4) << 8) | (j & 15);
#pragma unroll
        for (int i = 0; i < 16; ++i)
            buf[sw(idxD + (perm16(i) << 4))] = a[i];
    }
    __syncthreads();

    // ---- stage 2 (Ns = 256): idxD = j, coalesced global store ----
#pragma unroll
    for (int r = 0; r < 16; ++r)
        a[r] = buf[sw(j + (r << 8))];
    twiddle16<256>(a, j);
    dft16(a);
#pragma unroll
    for (int i = 0; i < 16; ++i) {
        const int idx = j + (perm16(i) << 8);
        float re, im; unc(a[i], re, im);
        yre[base + idx] = re;
        yim[base + idx] = im;
    }
}

extern "C" void kernel_launch(void* const* d_in, const int* in_sizes, int n_in,
                              void* d_out, int out_size)
{
    const float* xre = (const float*)d_in[0];
    const float* xim = (const float*)d_in[1];
    float*       out = (float*)d_out;

    const int rows = in_sizes[0] / FFT_N;      // 4096
    float* yre = out;
    float* yim = out + (size_t)rows * FFT_N;   // output tuple: [y_re | y_im]

    fft4096_r16<<<rows, TPB>>>(xre, xim, yre, yim);
}